// round 15
// baseline (speedup 1.0000x reference)
#include <cuda_runtime.h>
#include <stdint.h>

#define N_USERS 200000
#define N_ITEMS 100000
#define N_NODES 300000
#define N_EDGES 4800000
#define EMB 64
#define BATCH 4096
#define N_SEL 8192
#define CAP 128
#define NWORDS ((N_NODES + 31) / 32)

// Scratch (device globals; zero-initialized at module load).
// All launches perform full, idempotent recomputation: claim re-writes the
// same bits/slots every call, scan rebuilds g_cnt/g_list, acc rebuilds out.
__device__ unsigned g_bits[NWORDS];      // batch membership bitmap
__device__ int      g_slot[N_NODES];     // node -> slot+1 via atomicMax
__device__ int      g_cnt[N_SEL];
__device__ uint2    g_list[N_SEL * CAP];

// K1: zero counters + claim slots (winner = max slot id, deterministic).
__global__ void k_claim(const int* __restrict__ user_id,
                        const int* __restrict__ item_id) {
    int b = blockIdx.x * blockDim.x + threadIdx.x;
    if (b >= N_SEL) return;
    g_cnt[b] = 0;
    int node = (b < BATCH) ? user_id[b] : N_USERS + item_id[b - BATCH];
    atomicOr(&g_bits[node >> 5], 1u << (node & 31));
    atomicMax(&g_slot[node], b + 1);
}

// K2: coalesced edge scan, 4 edges/thread (proven R9 body).
__global__ void k_scan(const int*   __restrict__ adj_row,
                       const int*   __restrict__ adj_col,
                       const float* __restrict__ adj_vals) {
    int i = blockIdx.x * blockDim.x + threadIdx.x;
    if (i >= N_EDGES / 4) return;
    int4 r = ((const int4*)adj_row)[i];
    int e = i * 4;
#pragma unroll
    for (int k = 0; k < 4; k++) {
        int row = (k == 0) ? r.x : (k == 1) ? r.y : (k == 2) ? r.z : r.w;
        unsigned w = g_bits[row >> 5];
        if ((w >> (row & 31)) & 1u) {
            int s = g_slot[row] - 1;          // bit set => claimed => s >= 0
            int pos = atomicAdd(&g_cnt[s], 1);
            if (pos < CAP)
                g_list[s * CAP + pos] =
                    make_uint2((unsigned)adj_col[e + k],
                               __float_as_uint(adj_vals[e + k]));
        }
    }
}

// K3: one warp per slot, shfl-broadcast 4-edge groups (best-of-6 body,
// R9 verbatim). Winner indirection handles duplicates. No cleanup tail.
__global__ void k_acc(const int*   __restrict__ user_id,
                      const int*   __restrict__ item_id,
                      const float* __restrict__ user_emb,
                      const float* __restrict__ item_emb,
                      float*       __restrict__ out) {
    int s = blockIdx.x * (blockDim.x >> 5) + (threadIdx.x >> 5);
    int lane = threadIdx.x & 31;
    if (s >= N_SEL) return;

    int node = (s < BATCH) ? user_id[s] : N_USERS + item_id[s - BATCH];
    const float* xp = (node < N_USERS)
        ? user_emb + (size_t)node * EMB
        : item_emb + (size_t)(node - N_USERS) * EMB;
    float2 x2 = ((const float2*)xp)[lane];
    float ax = 2.0f * x2.x;
    float ay = 2.0f * x2.y;

    int w = g_slot[node] - 1;                 // winner slot for this node
    int n = g_cnt[w];
    if (n > CAP) n = CAP;

    for (int base = 0; base < n; base += 32) {
        uint2 ent = make_uint2(0u, 0u);
        if (base + lane < n) ent = g_list[w * CAP + base + lane];
        int m = n - base;
        if (m > 32) m = 32;

        int k = 0;
        for (; k + 4 <= m; k += 4) {          // unpredicated 4-edge groups
            float  vv[4];
            float2 rr[4];
#pragma unroll
            for (int j = 0; j < 4; j++) {
                int col = __shfl_sync(0xffffffffu, (int)ent.x, k + j);
                vv[j] = __uint_as_float(
                    __shfl_sync(0xffffffffu, ent.y, k + j));
                const float2* cp2 = (col < N_USERS)
                    ? (const float2*)(user_emb + (size_t)col * EMB)
                    : (const float2*)(item_emb + (size_t)(col - N_USERS) * EMB);
                rr[j] = cp2[lane];             // 4 independent 256B loads
            }
#pragma unroll
            for (int j = 0; j < 4; j++) {
                ax = fmaf(vv[j], rr[j].x, ax);
                ay = fmaf(vv[j], rr[j].y, ay);
            }
        }
        for (; k < m; k++) {                   // scalar tail
            int   col = __shfl_sync(0xffffffffu, (int)ent.x, k);
            float val = __uint_as_float(__shfl_sync(0xffffffffu, ent.y, k));
            const float2* cp2 = (col < N_USERS)
                ? (const float2*)(user_emb + (size_t)col * EMB)
                : (const float2*)(item_emb + (size_t)(col - N_USERS) * EMB);
            float2 r = cp2[lane];
            ax = fmaf(val, r.x, ax);
            ay = fmaf(val, r.y, ay);
        }
    }
    ((float2*)out)[(size_t)s * 32 + lane] = make_float2(ax, ay);
}

extern "C" void kernel_launch(void* const* d_in, const int* in_sizes, int n_in,
                              void* d_out, int out_size) {
    const float* user_emb = (const float*)d_in[0];
    const float* item_emb = (const float*)d_in[1];
    const int*   adj_row  = (const int*)d_in[2];
    const int*   adj_col  = (const int*)d_in[3];
    const float* adj_vals = (const float*)d_in[4];
    const int*   user_id  = (const int*)d_in[5];
    const int*   item_id  = (const int*)d_in[6];
    float*       out      = (float*)d_out;

    k_claim<<<32, 256>>>(user_id, item_id);
    k_scan <<<(N_EDGES / 4 + 255) / 256, 256>>>(adj_row, adj_col, adj_vals);
    k_acc  <<<N_SEL / 8, 256>>>(user_id, item_id, user_emb, item_emb, out);
}

// round 16
// speedup vs baseline: 1.2777x; 1.2777x over previous
#include <cuda_runtime.h>
#include <stdint.h>

#define N_USERS 200000
#define N_ITEMS 100000
#define N_NODES 300000
#define N_EDGES 4800000
#define EMB 64
#define BATCH 4096
#define N_SEL 8192
#define CAP 128
#define NWORDS ((N_NODES + 31) / 32)

// Scratch (device globals; zero-initialized at module load)
__device__ unsigned           g_bits[NWORDS];     // batch membership bitmap
__device__ unsigned long long g_slotv[N_NODES];   // (gen<<13)|slot, gen-tagged
__device__ int                g_cnt[N_SEL];
__device__ uint2              g_list[N_SEL * CAP];
__device__ unsigned long long g_gen;              // completed-launch counter

// K1: claim slots with generation tags (no clearing needed) + zero counters.
// Winner among duplicate nodes = max slot id (deterministic).
__global__ void k_claim(const int* __restrict__ user_id,
                        const int* __restrict__ item_id) {
    int b = blockIdx.x * blockDim.x + threadIdx.x;
    if (b >= N_SEL) return;
    g_cnt[b] = 0;
    int node = (b < BATCH) ? user_id[b] : N_USERS + item_id[b - BATCH];
    unsigned long long tag = ((g_gen + 1ULL) << 13) | (unsigned long long)b;
    atomicOr(&g_bits[node >> 5], 1u << (node & 31));
    atomicMax(&g_slotv[node], tag);
}

// K2: coalesced edge scan (int4), L1-cached global bitmap filter,
// compact selected edges into per-slot lists.
__global__ void k_scan(const int*   __restrict__ adj_row,
                       const int*   __restrict__ adj_col,
                       const float* __restrict__ adj_vals) {
    int i = blockIdx.x * blockDim.x + threadIdx.x;   // 4 edges per thread
    if (i >= N_EDGES / 4) return;
    int4 r = ((const int4*)adj_row)[i];
    int e = i * 4;
#pragma unroll
    for (int k = 0; k < 4; k++) {
        int row = (k == 0) ? r.x : (k == 1) ? r.y : (k == 2) ? r.z : r.w;
        unsigned w = g_bits[row >> 5];
        if ((w >> (row & 31)) & 1u) {
            // bit set => claimed THIS launch => tag is current
            int s = (int)(g_slotv[row] & 8191ULL);
            int pos = atomicAdd(&g_cnt[s], 1);
            if (pos < CAP)
                g_list[s * CAP + pos] =
                    make_uint2((unsigned)adj_col[e + k],
                               __float_as_uint(adj_vals[e + k]));
        }
    }
}

// K3: one warp per slot, winner indirection, float2 loads, 4-edge MLP
// groups. Tail: clear this node's bit; slot 0 bumps gen.
__global__ void k_acc(const int*   __restrict__ user_id,
                      const int*   __restrict__ item_id,
                      const float* __restrict__ user_emb,
                      const float* __restrict__ item_emb,
                      float*       __restrict__ out) {
    int s = blockIdx.x * (blockDim.x >> 5) + (threadIdx.x >> 5);
    int lane = threadIdx.x & 31;
    if (s >= N_SEL) return;

    int node = (s < BATCH) ? user_id[s] : N_USERS + item_id[s - BATCH];
    const float* xp = (node < N_USERS)
        ? user_emb + (size_t)node * EMB
        : item_emb + (size_t)(node - N_USERS) * EMB;
    float2 x2 = ((const float2*)xp)[lane];
    float ax = 2.0f * x2.x;
    float ay = 2.0f * x2.y;

    int w = (int)(g_slotv[node] & 8191ULL);   // winner slot for this node
    int n = g_cnt[w];
    if (n > CAP) n = CAP;

    for (int base = 0; base < n; base += 32) {
        uint2 ent = make_uint2(0u, 0u);
        if (base + lane < n) ent = g_list[w * CAP + base + lane];
        int m = n - base;
        if (m > 32) m = 32;

        int k = 0;
        for (; k + 4 <= m; k += 4) {          // unpredicated 4-edge groups
            float  vv[4];
            float2 rr[4];
#pragma unroll
            for (int j = 0; j < 4; j++) {
                int col = __shfl_sync(0xffffffffu, (int)ent.x, k + j);
                vv[j] = __uint_as_float(
                    __shfl_sync(0xffffffffu, ent.y, k + j));
                const float2* cp2 = (col < N_USERS)
                    ? (const float2*)(user_emb + (size_t)col * EMB)
                    : (const float2*)(item_emb + (size_t)(col - N_USERS) * EMB);
                rr[j] = cp2[lane];             // 4 independent 256B loads
            }
#pragma unroll
            for (int j = 0; j < 4; j++) {
                ax = fmaf(vv[j], rr[j].x, ax);
                ay = fmaf(vv[j], rr[j].y, ay);
            }
        }
        for (; k < m; k++) {                   // scalar tail
            int   col = __shfl_sync(0xffffffffu, (int)ent.x, k);
            float val = __uint_as_float(__shfl_sync(0xffffffffu, ent.y, k));
            const float2* cp2 = (col < N_USERS)
                ? (const float2*)(user_emb + (size_t)col * EMB)
                : (const float2*)(item_emb + (size_t)(col - N_USERS) * EMB);
            float2 r = cp2[lane];
            ax = fmaf(val, r.x, ax);
            ay = fmaf(val, r.y, ay);
        }
    }
    ((float2*)out)[(size_t)s * 32 + lane] = make_float2(ax, ay);

    // cleanup for next replay: clear this node's bit (idempotent)
    if (lane == 0) {
        atomicAnd(&g_bits[node >> 5], ~(1u << (node & 31)));
        if (s == 0) atomicAdd(&g_gen, 1ULL);   // next launch uses gen+1
    }
}

extern "C" void kernel_launch(void* const* d_in, const int* in_sizes, int n_in,
                              void* d_out, int out_size) {
    const float* user_emb = (const float*)d_in[0];
    const float* item_emb = (const float*)d_in[1];
    const int*   adj_row  = (const int*)d_in[2];
    const int*   adj_col  = (const int*)d_in[3];
    const float* adj_vals = (const float*)d_in[4];
    const int*   user_id  = (const int*)d_in[5];
    const int*   item_id  = (const int*)d_in[6];
    float*       out      = (float*)d_out;

    k_claim<<<32, 256>>>(user_id, item_id);
    k_scan <<<(N_EDGES / 4 + 255) / 256, 256>>>(adj_row, adj_col, adj_vals);
    k_acc  <<<N_SEL / 8, 256>>>(user_id, item_id, user_emb, item_emb, out);
}